// round 1
// baseline (speedup 1.0000x reference)
#include <cuda_runtime.h>
#include <math.h>

#define H 2048
#define N 16384
#define D 1024
#define EPSV 1e-8f
#define DIMSZ (5 + 3*D)   // 3077

// ---- scratch (no allocs allowed; __device__ globals) ----
__device__ float g_dim[DIMSZ];
__device__ float g_k[D];
__device__ float g_erase[D];
__device__ float g_add[D];
__device__ float g_normk;
__device__ float g_s[N];
__device__ float g_gate[N];
__device__ float g_wg[N];

__device__ __forceinline__ float warp_sum(float v) {
#pragma unroll
    for (int o = 16; o; o >>= 1) v += __shfl_xor_sync(0xffffffffu, v, o);
    return v;
}
__device__ __forceinline__ float warp_max(float v) {
#pragma unroll
    for (int o = 16; o; o >>= 1) v = fmaxf(v, __shfl_xor_sync(0xffffffffu, v, o));
    return v;
}

// ---------------------------------------------------------------------------
// Kernel A: dim_out = W_dim @ hidden + b_dim   (3077 rows x 2048)
// ---------------------------------------------------------------------------
__global__ void k_dim(const float* __restrict__ W, const float* __restrict__ h,
                      const float* __restrict__ b) {
    int row = blockIdx.x;
    const float4* w4 = reinterpret_cast<const float4*>(W + (size_t)row * H);
    const float4* h4 = reinterpret_cast<const float4*>(h);
    float s = 0.f;
#pragma unroll 2
    for (int j = threadIdx.x; j < H / 4; j += 256) {
        float4 w = w4[j], x = h4[j];
        s += w.x * x.x + w.y * x.y + w.z * x.z + w.w * x.w;
    }
    __shared__ float red[8];
    s = warp_sum(s);
    if ((threadIdx.x & 31) == 0) red[threadIdx.x >> 5] = s;
    __syncthreads();
    if (threadIdx.x < 8) {
        float v = red[threadIdx.x];
#pragma unroll
        for (int o = 4; o; o >>= 1) v += __shfl_xor_sync(0xffu, v, o);
        if (threadIdx.x == 0) g_dim[row] = v + b[row];
    }
}

// ---------------------------------------------------------------------------
// Prep: aligned copies of k/erase/add, compute ||k||.  <<<1,1024>>>
// ---------------------------------------------------------------------------
__global__ void k_prep() {
    int t = threadIdx.x;
    float kv = g_dim[5 + t];
    g_k[t] = kv;
    g_erase[t] = g_dim[5 + D + t];
    g_add[t] = g_dim[5 + 2 * D + t];
    __shared__ float red[32];
    float s = warp_sum(kv * kv);
    if ((t & 31) == 0) red[t >> 5] = s;
    __syncthreads();
    if (t < 32) {
        float v = red[t];
        v = warp_sum(v);
        if (t == 0) g_normk = sqrtf(v);
    }
}

// ---------------------------------------------------------------------------
// Kernel B (fused heavy pass): per row i of memory:
//   dot(mem_i, k), ||mem_i||^2  (same loads) and gate GEMV dot(W_gate_i, h)
//   -> g_s[i] = beta * cosine_sim, g_gate[i] = sigmoid(gate_out)
// <<<N, 256>>>
// ---------------------------------------------------------------------------
__global__ void k_row(const float* __restrict__ mem, const float* __restrict__ Wg,
                      const float* __restrict__ h, const float* __restrict__ bg) {
    int row = blockIdx.x;
    int t = threadIdx.x;
    const float4* m4 = reinterpret_cast<const float4*>(mem + (size_t)row * D);
    const float4* k4 = reinterpret_cast<const float4*>(g_k);
    float d1, d2;
    {
        float4 m = m4[t], kk = k4[t];   // D/4 == 256 == blockDim: one vec each
        d1 = m.x * kk.x + m.y * kk.y + m.z * kk.z + m.w * kk.w;
        d2 = m.x * m.x + m.y * m.y + m.z * m.z + m.w * m.w;
    }
    const float4* w4 = reinterpret_cast<const float4*>(Wg + (size_t)row * H);
    const float4* h4 = reinterpret_cast<const float4*>(h);
    float d3 = 0.f;
#pragma unroll 2
    for (int j = t; j < H / 4; j += 256) {
        float4 w = w4[j], x = h4[j];
        d3 += w.x * x.x + w.y * x.y + w.z * x.z + w.w * x.w;
    }
    __shared__ float r1[8], r2[8], r3[8];
    d1 = warp_sum(d1); d2 = warp_sum(d2); d3 = warp_sum(d3);
    int w = t >> 5;
    if ((t & 31) == 0) { r1[w] = d1; r2[w] = d2; r3[w] = d3; }
    __syncthreads();
    if (t == 0) {
        float a = 0.f, n2 = 0.f, c = 0.f;
#pragma unroll
        for (int i = 0; i < 8; i++) { a += r1[i]; n2 += r2[i]; c += r3[i]; }
        float sim = a / (sqrtf(n2) * g_normk + EPSV);
        g_s[row] = g_dim[0] * sim;
        float go = c + bg[row];
        g_gate[row] = 1.f / (1.f + expf(-go));
    }
}

// ---------------------------------------------------------------------------
// Kernel C1: softmax over s, then w_g = gate*w_c + (1-gate)*last_weight.
// Single block, 1024 threads, 16 elements/thread (strided).
// ---------------------------------------------------------------------------
__global__ void k_soft(const float* __restrict__ lw) {
    int t = threadIdx.x;
    __shared__ float red[32];
    float sv[16];
    float mx = -1e30f;
#pragma unroll
    for (int j = 0; j < 16; j++) {
        sv[j] = g_s[t + 1024 * j];
        mx = fmaxf(mx, sv[j]);
    }
    mx = warp_max(mx);
    if ((t & 31) == 0) red[t >> 5] = mx;
    __syncthreads();
    if (t < 32) { float v = red[t]; v = warp_max(v); if (t == 0) red[0] = v; }
    __syncthreads();
    mx = red[0];
    __syncthreads();
    float sum = 0.f;
#pragma unroll
    for (int j = 0; j < 16; j++) {
        sv[j] = expf(sv[j] - mx);
        sum += sv[j];
    }
    sum = warp_sum(sum);
    if ((t & 31) == 0) red[t >> 5] = sum;
    __syncthreads();
    if (t < 32) { float v = red[t]; v = warp_sum(v); if (t == 0) red[0] = v; }
    __syncthreads();
    float inv = 1.f / red[0];
#pragma unroll
    for (int j = 0; j < 16; j++) {
        int i = t + 1024 * j;
        float wc = sv[j] * inv;
        float gg = g_gate[i];
        g_wg[i] = gg * wc + (1.f - gg) * lw[i];
    }
}

// ---------------------------------------------------------------------------
// Kernel C2: shift convolution (circular), pow(gamma), normalize -> weight.
// Writes weight region of d_out, zeroes memory_read region. <<<1,1024>>>
// ---------------------------------------------------------------------------
__global__ void k_weight(float* __restrict__ out) {
    int t = threadIdx.x;
    float a0 = g_dim[2], a1 = g_dim[3], a2 = g_dim[4];
    float mm = fmaxf(a0, fmaxf(a1, a2));
    float e0 = expf(a0 - mm), e1 = expf(a1 - mm), e2 = expf(a2 - mm);
    float inv3 = 1.f / (e0 + e1 + e2);
    float sh0 = e0 * inv3, sh1 = e1 * inv3, sh2 = e2 * inv3;
    float gamma = g_dim[1];

    __shared__ float red[32];
    float wp[16];
    float sum = 0.f;
#pragma unroll
    for (int j = 0; j < 16; j++) {
        int i = t + 1024 * j;
        float wt = sh0 * g_wg[(i - 1) & (N - 1)] + sh1 * g_wg[i]
                 + sh2 * g_wg[(i + 1) & (N - 1)];
        wp[j] = powf(wt, gamma);
        sum += wp[j];
    }
    sum = warp_sum(sum);
    if ((t & 31) == 0) red[t >> 5] = sum;
    __syncthreads();
    if (t < 32) { float v = red[t]; v = warp_sum(v); if (t == 0) red[0] = v; }
    __syncthreads();
    float inv = 1.f / red[0];
#pragma unroll
    for (int j = 0; j < 16; j++) {
        out[D + t + 1024 * j] = wp[j] * inv;   // weight region [D, D+N)
    }
    out[t] = 0.f;  // zero memory_read region [0, D)
}

// ---------------------------------------------------------------------------
// Kernel E: new_memory + memory_read.
// 1024 blocks x 256 threads; block handles 16 rows; thread owns 1 float4 col.
// memory_read accumulated in registers across rows, one atomic burst at end.
// ---------------------------------------------------------------------------
__global__ void k_update(const float* __restrict__ mem, float* __restrict__ out) {
    int t = threadIdx.x;                       // 0..255 -> cols 4t..4t+3
    const float* weight = out + D;             // weight region
    float4* newm = reinterpret_cast<float4*>(out + D + N);
    const float4* m4 = reinterpret_cast<const float4*>(mem);
    float4 e4 = reinterpret_cast<const float4*>(g_erase)[t];
    float4 a4 = reinterpret_cast<const float4*>(g_add)[t];
    float4 acc = make_float4(0.f, 0.f, 0.f, 0.f);
    int base = blockIdx.x * 16;
#pragma unroll 4
    for (int r = 0; r < 16; r++) {
        int row = base + r;
        float w = __ldg(weight + row);
        float4 m = m4[(size_t)row * 256 + t];
        acc.x += w * m.x; acc.y += w * m.y; acc.z += w * m.z; acc.w += w * m.w;
        float4 nm;
        nm.x = m.x * (1.f - w * e4.x) + w * a4.x;
        nm.y = m.y * (1.f - w * e4.y) + w * a4.y;
        nm.z = m.z * (1.f - w * e4.z) + w * a4.z;
        nm.w = m.w * (1.f - w * e4.w) + w * a4.w;
        newm[(size_t)row * 256 + t] = nm;
    }
    atomicAdd(&out[4 * t + 0], acc.x);
    atomicAdd(&out[4 * t + 1], acc.y);
    atomicAdd(&out[4 * t + 2], acc.z);
    atomicAdd(&out[4 * t + 3], acc.w);
}

// ---------------------------------------------------------------------------
extern "C" void kernel_launch(void* const* d_in, const int* in_sizes, int n_in,
                              void* d_out, int out_size) {
    const float* hidden = (const float*)d_in[0];
    const float* lw     = (const float*)d_in[1];
    const float* mem    = (const float*)d_in[2];
    const float* Wd     = (const float*)d_in[3];
    const float* bd     = (const float*)d_in[4];
    const float* Wg     = (const float*)d_in[5];
    const float* bg     = (const float*)d_in[6];
    float* out = (float*)d_out;

    k_dim<<<DIMSZ, 256>>>(Wd, hidden, bd);
    k_prep<<<1, 1024>>>();
    k_row<<<N, 256>>>(mem, Wg, hidden, bg);
    k_soft<<<1, 1024>>>(lw);
    k_weight<<<1, 1024>>>(out);
    k_update<<<N / 16, 256>>>(mem, out);
}

// round 2
// speedup vs baseline: 1.1520x; 1.1520x over previous
#include <cuda_runtime.h>
#include <math.h>

#define H 2048
#define N 16384
#define D 1024
#define EPSV 1e-8f
#define DIMSZ (5 + 3*D)   // 3077

// ---- scratch (__device__ globals; no allocs allowed) ----
__device__ float g_dim5[5];          // beta, gamma, shift logits
__device__ float g_k[D];
__device__ float g_erase[D];
__device__ float g_add[D];
__device__ float g_k2;               // ||k||^2 accumulator
__device__ float g_s[N];             // beta*sim, then exp values
__device__ float g_gate[N];
__device__ float g_wp[N];            // unnormalized w_tilde^gamma
__device__ unsigned g_smax_u;        // order-encoded float max
__device__ float g_sum;              // softmax denominator
__device__ float g_psum;             // pow-sum denominator

__device__ __forceinline__ float warp_sum(float v) {
#pragma unroll
    for (int o = 16; o; o >>= 1) v += __shfl_xor_sync(0xffffffffu, v, o);
    return v;
}

__device__ __forceinline__ unsigned fenc(float x) {
    unsigned u = __float_as_uint(x);
    return (u & 0x80000000u) ? ~u : (u | 0x80000000u);
}
__device__ __forceinline__ float fdec(unsigned k) {
    unsigned u = (k & 0x80000000u) ? (k ^ 0x80000000u) : ~k;
    return __uint_as_float(u);
}

// ---------------------------------------------------------------------------
// Init: zero accumulators + zero memory_read region of d_out. <<<1,1024>>>
// ---------------------------------------------------------------------------
__global__ void k_init(float* __restrict__ out) {
    int t = threadIdx.x;
    out[t] = 0.f;                    // memory_read region [0, D)
    if (t == 0) { g_k2 = 0.f; g_sum = 0.f; g_psum = 0.f; g_smax_u = 0u; }
}

// ---------------------------------------------------------------------------
// dim_out = W_dim @ hidden + b_dim, scattered into g_dim5 / g_k / g_erase /
// g_add; k-rows also accumulate ||k||^2. <<<DIMSZ, 256>>>
// ---------------------------------------------------------------------------
__global__ void k_dim(const float* __restrict__ W, const float* __restrict__ h,
                      const float* __restrict__ b) {
    int row = blockIdx.x;
    const float4* w4 = reinterpret_cast<const float4*>(W + (size_t)row * H);
    const float4* h4 = reinterpret_cast<const float4*>(h);
    float s = 0.f;
#pragma unroll 2
    for (int j = threadIdx.x; j < H / 4; j += 256) {
        float4 w = w4[j], x = h4[j];
        s += w.x * x.x + w.y * x.y + w.z * x.z + w.w * x.w;
    }
    __shared__ float red[8];
    s = warp_sum(s);
    if ((threadIdx.x & 31) == 0) red[threadIdx.x >> 5] = s;
    __syncthreads();
    if (threadIdx.x == 0) {
        float v = 0.f;
#pragma unroll
        for (int i = 0; i < 8; i++) v += red[i];
        v += b[row];
        if (row < 5)              g_dim5[row] = v;
        else if (row < 5 + D)   { g_k[row - 5] = v; atomicAdd(&g_k2, v * v); }
        else if (row < 5 + 2*D)   g_erase[row - 5 - D] = v;
        else                      g_add[row - 5 - 2*D] = v;
    }
}

// ---------------------------------------------------------------------------
// Fused heavy pass per memory row i:
//   dot(mem_i,k), ||mem_i||^2 (shared loads), gate GEMV dot(Wg_i, h)
//   -> g_s[i] = beta*cos_sim, g_gate[i] = sigmoid, atomicMax running max.
// <<<N, 256>>>
// ---------------------------------------------------------------------------
__global__ void k_row(const float* __restrict__ mem, const float* __restrict__ Wg,
                      const float* __restrict__ h, const float* __restrict__ bg) {
    int row = blockIdx.x;
    int t = threadIdx.x;
    const float4* m4 = reinterpret_cast<const float4*>(mem + (size_t)row * D);
    const float4* k4 = reinterpret_cast<const float4*>(g_k);
    float d1, d2;
    {
        float4 m = m4[t], kk = k4[t];   // D/4 == 256 == blockDim
        d1 = m.x * kk.x + m.y * kk.y + m.z * kk.z + m.w * kk.w;
        d2 = m.x * m.x + m.y * m.y + m.z * m.z + m.w * m.w;
    }
    const float4* w4 = reinterpret_cast<const float4*>(Wg + (size_t)row * H);
    const float4* h4 = reinterpret_cast<const float4*>(h);
    float d3 = 0.f;
#pragma unroll 2
    for (int j = t; j < H / 4; j += 256) {
        float4 w = w4[j], x = h4[j];
        d3 += w.x * x.x + w.y * x.y + w.z * x.z + w.w * x.w;
    }
    __shared__ float r1[8], r2[8], r3[8];
    d1 = warp_sum(d1); d2 = warp_sum(d2); d3 = warp_sum(d3);
    int w = t >> 5;
    if ((t & 31) == 0) { r1[w] = d1; r2[w] = d2; r3[w] = d3; }
    __syncthreads();
    if (t == 0) {
        float a = 0.f, n2 = 0.f, c = 0.f;
#pragma unroll
        for (int i = 0; i < 8; i++) { a += r1[i]; n2 += r2[i]; c += r3[i]; }
        float sim = a / (sqrtf(n2) * sqrtf(g_k2) + EPSV);
        float sv = g_dim5[0] * sim;
        g_s[row] = sv;
        atomicMax(&g_smax_u, fenc(sv));
        float go = c + bg[row];
        g_gate[row] = 1.f / (1.f + expf(-go));
    }
}

// ---------------------------------------------------------------------------
// exp pass spread over 64 SMs: e = exp(s - max); partial sums -> g_sum.
// <<<64, 256>>>
// ---------------------------------------------------------------------------
__global__ void k_exp() {
    int i = blockIdx.x * 256 + threadIdx.x;
    float mx = fdec(g_smax_u);
    float e = expf(g_s[i] - mx);
    g_s[i] = e;
    __shared__ float red[8];
    float s = warp_sum(e);
    if ((threadIdx.x & 31) == 0) red[threadIdx.x >> 5] = s;
    __syncthreads();
    if (threadIdx.x == 0) {
        float v = 0.f;
#pragma unroll
        for (int k = 0; k < 8; k++) v += red[k];
        atomicAdd(&g_sum, v);
    }
}

// ---------------------------------------------------------------------------
// Shift conv + pow, spread over 64 SMs. Recomputes w_g at i-1,i,i+1 from
// (e, gate, lw) — pure cache hits, avoids an extra global barrier.
// wp stored unnormalized; partial pow-sums -> g_psum. <<<64, 256>>>
// ---------------------------------------------------------------------------
__device__ __forceinline__ float wg_at(int j, float inv_sum,
                                       const float* __restrict__ lw) {
    j &= (N - 1);
    float g = g_gate[j];
    return g * g_s[j] * inv_sum + (1.f - g) * lw[j];
}

__global__ void k_shift(const float* __restrict__ lw) {
    int i = blockIdx.x * 256 + threadIdx.x;
    float a0 = g_dim5[2], a1 = g_dim5[3], a2 = g_dim5[4];
    float mm = fmaxf(a0, fmaxf(a1, a2));
    float e0 = expf(a0 - mm), e1 = expf(a1 - mm), e2 = expf(a2 - mm);
    float inv3 = 1.f / (e0 + e1 + e2);
    float sh0 = e0 * inv3, sh1 = e1 * inv3, sh2 = e2 * inv3;
    float gamma = g_dim5[1];
    float inv_sum = 1.f / g_sum;

    float wt = sh0 * wg_at(i - 1, inv_sum, lw)
             + sh1 * wg_at(i,     inv_sum, lw)
             + sh2 * wg_at(i + 1, inv_sum, lw);
    float wp = powf(wt, gamma);
    g_wp[i] = wp;

    __shared__ float red[8];
    float s = warp_sum(wp);
    if ((threadIdx.x & 31) == 0) red[threadIdx.x >> 5] = s;
    __syncthreads();
    if (threadIdx.x == 0) {
        float v = 0.f;
#pragma unroll
        for (int k = 0; k < 8; k++) v += red[k];
        atomicAdd(&g_psum, v);
    }
}

// ---------------------------------------------------------------------------
// new_memory + memory_read + weight output, all fused.
// 1024 blocks x 256 threads; block handles 16 rows; thread owns 1 float4 col.
// <<<N/16, 256>>>
// ---------------------------------------------------------------------------
__global__ void k_update(const float* __restrict__ mem, float* __restrict__ out) {
    int t = threadIdx.x;                       // 0..255 -> cols 4t..4t+3
    float inv = 1.f / g_psum;
    float4* newm = reinterpret_cast<float4*>(out + D + N);
    const float4* m4 = reinterpret_cast<const float4*>(mem);
    float4 e4 = reinterpret_cast<const float4*>(g_erase)[t];
    float4 a4 = reinterpret_cast<const float4*>(g_add)[t];
    float4 acc = make_float4(0.f, 0.f, 0.f, 0.f);
    int base = blockIdx.x * 16;
    if (t < 16) out[D + base + t] = g_wp[base + t] * inv;   // weight output
#pragma unroll 4
    for (int r = 0; r < 16; r++) {
        int row = base + r;
        float w = g_wp[row] * inv;
        float4 m = m4[(size_t)row * 256 + t];
        acc.x += w * m.x; acc.y += w * m.y; acc.z += w * m.z; acc.w += w * m.w;
        float4 nm;
        nm.x = m.x * (1.f - w * e4.x) + w * a4.x;
        nm.y = m.y * (1.f - w * e4.y) + w * a4.y;
        nm.z = m.z * (1.f - w * e4.z) + w * a4.z;
        nm.w = m.w * (1.f - w * e4.w) + w * a4.w;
        newm[(size_t)row * 256 + t] = nm;
    }
    atomicAdd(&out[4 * t + 0], acc.x);
    atomicAdd(&out[4 * t + 1], acc.y);
    atomicAdd(&out[4 * t + 2], acc.z);
    atomicAdd(&out[4 * t + 3], acc.w);
}

// ---------------------------------------------------------------------------
extern "C" void kernel_launch(void* const* d_in, const int* in_sizes, int n_in,
                              void* d_out, int out_size) {
    const float* hidden = (const float*)d_in[0];
    const float* lw     = (const float*)d_in[1];
    const float* mem    = (const float*)d_in[2];
    const float* Wd     = (const float*)d_in[3];
    const float* bd     = (const float*)d_in[4];
    const float* Wg     = (const float*)d_in[5];
    const float* bg     = (const float*)d_in[6];
    float* out = (float*)d_out;

    k_init  <<<1, 1024>>>(out);
    k_dim   <<<DIMSZ, 256>>>(Wd, hidden, bd);
    k_row   <<<N, 256>>>(mem, Wg, hidden, bg);
    k_exp   <<<N / 256, 256>>>();
    k_shift <<<N / 256, 256>>>(lw);
    k_update<<<N / 16, 256>>>(mem, out);
}